// round 9
// baseline (speedup 1.0000x reference)
#include <cuda_runtime.h>

#define N_NODES 50000
#define N_REL   1000
#define D       128
#define NNZ_MAX 800000

#define NB       592          // mega-kernel grid: exactly 4 blocks/SM (co-resident)
#define Q        128          // edges per gather warp
#define SCAN_NB  ((N_NODES + 255) / 256)   // 196 scan blocks (subset of NB)

// Scratch (allocation-free rule: __device__ globals)
__device__ float g_exp_lr[N_REL];
__device__ float g_coef[N_REL];
__device__ float g_S;
__device__ int   g_cnt[N_NODES];
__device__ int   g_bsum[SCAN_NB];
__device__ int   g_offs[N_NODES + 1];
__device__ int   g_tick;                              // monotonic ticket barrier
__device__ __align__(16) int g_rank[NNZ_MAX];
__device__ __align__(16) unsigned long long g_edges[NNZ_MAX]; // rel<<32|col<<16|row

// Monotonic grid barrier: every launch adds exactly NB per barrier, so the
// counter is always a multiple of NB at phase boundaries; no reset needed.
__device__ __forceinline__ void grid_bar() {
    __syncthreads();
    __threadfence();
    if (threadIdx.x == 0) {
        const int t = atomicAdd(&g_tick, 1);
        const int target = (t / NB + 1) * NB;
        while (atomicAdd(&g_tick, 0) < target) {}
    }
    __syncthreads();
}

// ---------------------------------------------------------------------------
// K1 (mega-prep): A zero+scores | B hist+rank+denominator | C scan+coef |
//                 D flat-edge write + zero atomic-candidate out rows.
// ---------------------------------------------------------------------------
__global__ void __launch_bounds__(256, 4)
k_prep(const float* __restrict__ dual, const float* __restrict__ w,
       const float* __restrict__ b,
       const int* __restrict__ rowp, const int* __restrict__ colp,
       const int* __restrict__ relp, int nnz, float* __restrict__ out) {
    const int tid  = blockIdx.x * blockDim.x + threadIdx.x;
    const int nthr = NB * 256;
    const int lane = threadIdx.x & 31;
    const int bid  = blockIdx.x;
    const int t    = threadIdx.x;
    __shared__ int   sm[256];
    __shared__ float smf[8];

    // ---- Phase A: zero counters + relation scores (warp/rel; shift=0 safe) ----
    if (tid == 0) g_S = 0.f;
    for (int i = tid; i < N_NODES; i += nthr) g_cnt[i] = 0;

    const int r = tid >> 5;
    if (r < N_REL) {
        const float4 a  = reinterpret_cast<const float4*>(dual + (size_t)r * D)[lane];
        const float4 ww = reinterpret_cast<const float4*>(w)[lane];
        float s = a.x * ww.x + a.y * ww.y + a.z * ww.z + a.w * ww.w;
#pragma unroll
        for (int o = 16; o > 0; o >>= 1) s += __shfl_xor_sync(0xffffffffu, s, o);
        if (lane == 0) {
            s += b[0];
            const float lr = (s > 0.f) ? s : 0.01f * s;
            g_exp_lr[r] = expf(lr);
        }
    }

    grid_bar();

    // ---- Phase B: histogram + per-edge rank + softmax denominator ----
    {
        const int nvec = nnz >> 2;
        const int4* row4 = reinterpret_cast<const int4*>(rowp);
        const int4* rel4 = reinterpret_cast<const int4*>(relp);
        int4* rank4 = reinterpret_cast<int4*>(g_rank);

        float s = 0.f;
        for (int i = tid; i < nvec; i += nthr) {
            const int4 r0 = __ldg(row4 + i);
            const int4 q0 = __ldg(rel4 + i);
            int4 rk;
            rk.x = atomicAdd(&g_cnt[r0.x], 1);
            rk.y = atomicAdd(&g_cnt[r0.y], 1);
            rk.z = atomicAdd(&g_cnt[r0.z], 1);
            rk.w = atomicAdd(&g_cnt[r0.w], 1);
            rank4[i] = rk;
            s += g_exp_lr[q0.x] + g_exp_lr[q0.y] + g_exp_lr[q0.z] + g_exp_lr[q0.w];
        }
        const int e0 = (nvec << 2) + tid;
        if (e0 < nnz) {
            g_rank[e0] = atomicAdd(&g_cnt[__ldg(rowp + e0)], 1);
            s += g_exp_lr[__ldg(relp + e0)];
        }
#pragma unroll
        for (int o = 16; o > 0; o >>= 1) s += __shfl_xor_sync(0xffffffffu, s, o);
        if ((t & 31) == 0) smf[t >> 5] = s;
        __syncthreads();
        if (t < 32) {
            float v = (t < 8) ? smf[t] : 0.f;
#pragma unroll
            for (int o = 4; o > 0; o >>= 1) v += __shfl_xor_sync(0xffffffffu, v, o);
            if (t == 0) atomicAdd(&g_S, v);
        }
    }

    grid_bar();

    // ---- Phase C: scan (blocks 0..195), coef normalize (block 200) ----
    int incl = 0, v = 0, gid = 0;
    if (bid < SCAN_NB) {
        gid = bid * 256 + t;
        v = (gid < N_NODES) ? __ldcg(&g_cnt[gid]) : 0;
        sm[t] = v;
        __syncthreads();
#pragma unroll
        for (int o = 1; o < 256; o <<= 1) {
            const int p = (t >= o) ? sm[t - o] : 0;
            __syncthreads();
            sm[t] += p;
            __syncthreads();
        }
        incl = sm[t];
        if (t == 255) g_bsum[bid] = incl;
    } else if (bid == 200) {
        const float invS = 1.0f / __ldcg(&g_S);
        for (int rr = t; rr < N_REL; rr += 256) g_coef[rr] = g_exp_lr[rr] * invS;
        if (t == 0) g_offs[N_NODES] = nnz;
    }

    grid_bar();

    if (bid < SCAN_NB) {
        // block base = sum of predecessors' totals
        sm[t] = (t < bid) ? __ldcg(&g_bsum[t]) : 0;
        __syncthreads();
#pragma unroll
        for (int o = 128; o > 0; o >>= 1) {
            if (t < o) sm[t] += sm[t + o];
            __syncthreads();
        }
        const int base = sm[0];
        if (gid < N_NODES) g_offs[gid] = base + incl - v;
    }

    grid_bar();

    // ---- Phase D1: write flat packed edges in CSR order (no atomics) ----
    {
        const int nvec = nnz >> 2;
        for (int i = tid; i < nvec; i += nthr) {
            const int4 rr = __ldg(reinterpret_cast<const int4*>(rowp) + i);
            const int4 cc = __ldg(reinterpret_cast<const int4*>(colp) + i);
            const int4 qq = __ldg(reinterpret_cast<const int4*>(relp) + i);
            const int4 rk = __ldcg(reinterpret_cast<const int4*>(g_rank) + i);
            const int p0 = __ldcg(&g_offs[rr.x]) + rk.x;
            const int p1 = __ldcg(&g_offs[rr.y]) + rk.y;
            const int p2 = __ldcg(&g_offs[rr.z]) + rk.z;
            const int p3 = __ldcg(&g_offs[rr.w]) + rk.w;
            g_edges[p0] = ((unsigned long long)qq.x << 32) | ((unsigned)cc.x << 16) | (unsigned)rr.x;
            g_edges[p1] = ((unsigned long long)qq.y << 32) | ((unsigned)cc.y << 16) | (unsigned)rr.y;
            g_edges[p2] = ((unsigned long long)qq.z << 32) | ((unsigned)cc.z << 16) | (unsigned)rr.z;
            g_edges[p3] = ((unsigned long long)qq.w << 32) | ((unsigned)cc.w << 16) | (unsigned)rr.w;
        }
        const int e0 = (nvec << 2) + tid;
        if (e0 < nnz) {
            const int row = __ldg(rowp + e0);
            const int pos = __ldcg(&g_offs[row]) + __ldcg(&g_rank[e0]);
            g_edges[pos] = ((unsigned long long)__ldg(relp + e0) << 32) |
                           ((unsigned)__ldg(colp + e0) << 16) | (unsigned)row;
        }
    }

    // ---- Phase D2: zero out-rows that gather will atomic into (or empty) ----
    {
        const int wglob  = (bid * 256 + t) >> 5;
        const int nwarps = (NB * 256) >> 5;
        for (int rrow = wglob; rrow < N_NODES; rrow += nwarps) {
            const int s = __ldcg(&g_offs[rrow]);
            const int e = __ldcg(&g_offs[rrow + 1]);
            const bool flag = (s == e) || (s % Q == 0) || (e % Q == 0) ||
                              (e == nnz) || ((s / Q) != ((e - 1) / Q));
            if (flag)
                reinterpret_cast<float4*>(out + (size_t)rrow * D)[lane] =
                    make_float4(0.f, 0.f, 0.f, 0.f);
        }
    }
}

// ---------------------------------------------------------------------------
// K2: edge-balanced gather. Each warp owns exactly Q consecutive CSR edges.
// Interior rows -> plain float4 store; first/last segment -> RED.v4 atomic
// (those rows pre-zeroed in K1-D2). Depth-1 feature prefetch for MLP.
// ---------------------------------------------------------------------------
__device__ __forceinline__ void flush_row(float* __restrict__ out, int row,
                                          const float4& a, bool atomic, int lane) {
    float* p = out + (size_t)row * D + lane * 4;
    if (atomic) {
        asm volatile("red.global.add.v4.f32 [%0], {%1, %2, %3, %4};"
                     :: "l"(p), "f"(a.x), "f"(a.y), "f"(a.z), "f"(a.w)
                     : "memory");
    } else {
        *reinterpret_cast<float4*>(p) = a;
    }
}

__global__ void __launch_bounds__(256)
k_gather(const float* __restrict__ inlayer, float* __restrict__ out, int nnz) {
    const int lane = threadIdx.x & 31;
    const int wid  = (blockIdx.x * blockDim.x + threadIdx.x) >> 5;
    const int base = wid * Q;
    if (base >= nnz) return;
    const int end = min(base + Q, nnz);

    unsigned long long ed = __ldg(&g_edges[base]);
    float4 v = __ldg(reinterpret_cast<const float4*>(
                         inlayer + (size_t)((ed >> 16) & 0xFFFFu) * D) + lane);
    float c = __ldg(&g_coef[(int)(ed >> 32)]);
    int currow = (int)(ed & 0xFFFFu);

    bool first = true;
    float4 acc = make_float4(0.f, 0.f, 0.f, 0.f);

    for (int i = base + 1; i <= end; i++) {
        unsigned long long edn = 0;
        float4 vn = make_float4(0.f, 0.f, 0.f, 0.f);
        float cn = 0.f;
        if (i < end) {
            edn = __ldg(&g_edges[i]);
            vn = __ldg(reinterpret_cast<const float4*>(
                           inlayer + (size_t)((edn >> 16) & 0xFFFFu) * D) + lane);
            cn = __ldg(&g_coef[(int)(edn >> 32)]);
        }
        // process current edge
        const int row = (int)(ed & 0xFFFFu);
        if (row != currow) {
            flush_row(out, currow, acc, first, lane);   // first segment: atomic
            first = false;
            acc = make_float4(0.f, 0.f, 0.f, 0.f);
            currow = row;
        }
        acc.x += c * v.x; acc.y += c * v.y; acc.z += c * v.z; acc.w += c * v.w;
        ed = edn; v = vn; c = cn;
    }
    flush_row(out, currow, acc, true, lane);            // last segment: atomic
}

// ---------------------------------------------------------------------------
// kernel_launch
// Inputs: 0 inlayer [N,D] f32 | 1 dual [R,D] f32 | 2 conv_w [D] f32
//         3 conv_b [1] f32    | 4 edge_idx [2,NNZ] i32 | 5 edge_rel [NNZ] i32
// Output: [N, D] f32
// ---------------------------------------------------------------------------
extern "C" void kernel_launch(void* const* d_in, const int* in_sizes, int n_in,
                              void* d_out, int out_size) {
    const float* inlayer = (const float*)d_in[0];
    const float* dual    = (const float*)d_in[1];
    const float* conv_w  = (const float*)d_in[2];
    const float* conv_b  = (const float*)d_in[3];
    const int*   eidx    = (const int*)d_in[4];
    const int*   erel    = (const int*)d_in[5];
    float*       out     = (float*)d_out;

    const int nnz = in_sizes[5];
    const int* rowp = eidx;
    const int* colp = eidx + nnz;

    k_prep<<<NB, 256>>>(dual, conv_w, conv_b, rowp, colp, erel, nnz, out);

    const int nwarps = (nnz + Q - 1) / Q;               // 6250
    k_gather<<<(nwarps + 7) / 8, 256>>>(inlayer, out, nnz);
}

// round 10
// speedup vs baseline: 1.0043x; 1.0043x over previous
#include <cuda_runtime.h>
#include <cuda_fp16.h>

#define N_NODES 50000
#define N_REL   1000
#define D       128
#define NNZ_MAX 800000

#define FUSE_NB  592          // fused kernel: exactly 4 blocks/SM -> co-resident
#define SCAN_BLK 512
#define SCAN_NB  ((N_NODES + SCAN_BLK - 1) / SCAN_BLK)   // 98 co-resident blocks

// Scratch (allocation-free rule: __device__ globals)
__device__ float g_exp_lr[N_REL];
__device__ float g_coef[N_REL];            // exp/S * 2^112 (magic-convert folded in)
__device__ float g_S;
__device__ int   g_cnt[N_NODES];
__device__ int   g_bsum[SCAN_NB];
__device__ int   g_tick1;                  // monotonic ticket barrier (K1, NB=592)
__device__ int   g_tick2;                  // monotonic ticket barrier (K2, NB=98)
__device__ int   g_offs[N_NODES + 1];
__device__ __align__(16) int g_rank[NNZ_MAX];
__device__ __align__(16) unsigned g_edges[NNZ_MAX];            // col | rel<<16
__device__ __align__(16) __half g_inh[(size_t)N_NODES * D];    // fp16 features

// Monotonic ticket barrier: counter only grows; each use consumes exactly NB
// increments, so phase boundaries are multiples of NB -> replay-safe, no reset.
template <int NBLK>
__device__ __forceinline__ void grid_bar(int* tick) {
    __syncthreads();
    __threadfence();
    if (threadIdx.x == 0) {
        const int t = atomicAdd(tick, 1);
        const int target = (t / NBLK + 1) * NBLK;
        while (atomicAdd(tick, 0) < target) {}
    }
    __syncthreads();
}

// ---------------------------------------------------------------------------
// K1 (fused): phase A: zero cnt/S + relation scores (warp/rel; shift=0 safe)
//                      + fp16 staging of inlayer (independent streams).
//             -- grid barrier --
//             phase B: row histogram (capturing per-edge rank) + denominator.
// ---------------------------------------------------------------------------
__global__ void __launch_bounds__(256, 4)
k_fused(const float* __restrict__ inlayer, const float* __restrict__ dual,
        const float* __restrict__ w, const float* __restrict__ b,
        const int* __restrict__ rowp, const int* __restrict__ relp, int nnz) {
    const int tid  = blockIdx.x * blockDim.x + threadIdx.x;
    const int nthr = FUSE_NB * 256;
    const int lane = threadIdx.x & 31;

    // ---- phase A ----
    if (tid == 0) g_S = 0.f;
    for (int i = tid; i < N_NODES; i += nthr) g_cnt[i] = 0;

    const int r = tid >> 5;
    if (r < N_REL) {
        const float4 a  = reinterpret_cast<const float4*>(dual + (size_t)r * D)[lane];
        const float4 ww = reinterpret_cast<const float4*>(w)[lane];
        float s = a.x * ww.x + a.y * ww.y + a.z * ww.z + a.w * ww.w;
#pragma unroll
        for (int o = 16; o > 0; o >>= 1) s += __shfl_xor_sync(0xffffffffu, s, o);
        if (lane == 0) {
            s += b[0];
            const float lr = (s > 0.f) ? s : 0.01f * s;
            g_exp_lr[r] = expf(lr);
        }
    }

    // fp16 staging: 6.4M floats = 1.6M float4 -> uint2 (4 halves)
    {
        const int nv = (N_NODES * D) / 4;
        const float4* in4 = reinterpret_cast<const float4*>(inlayer);
        uint2* out2 = reinterpret_cast<uint2*>(g_inh);
        for (int i = tid; i < nv; i += nthr) {
            const float4 v = __ldg(in4 + i);
            const __half2 h01 = __floats2half2_rn(v.x, v.y);
            const __half2 h23 = __floats2half2_rn(v.z, v.w);
            uint2 p;
            p.x = *reinterpret_cast<const unsigned*>(&h01);
            p.y = *reinterpret_cast<const unsigned*>(&h23);
            out2[i] = p;
        }
    }

    grid_bar<FUSE_NB>(&g_tick1);

    // ---- phase B ----
    const int nvec = nnz >> 2;
    const int4* row4 = reinterpret_cast<const int4*>(rowp);
    const int4* rel4 = reinterpret_cast<const int4*>(relp);
    int4* rank4 = reinterpret_cast<int4*>(g_rank);

    float s = 0.f;
    for (int i = tid; i < nvec; i += nthr) {
        const int4 r0 = __ldg(row4 + i);
        const int4 q0 = __ldg(rel4 + i);
        int4 rk;
        rk.x = atomicAdd(&g_cnt[r0.x], 1);
        rk.y = atomicAdd(&g_cnt[r0.y], 1);
        rk.z = atomicAdd(&g_cnt[r0.z], 1);
        rk.w = atomicAdd(&g_cnt[r0.w], 1);
        rank4[i] = rk;
        s += g_exp_lr[q0.x] + g_exp_lr[q0.y] + g_exp_lr[q0.z] + g_exp_lr[q0.w];
    }
    const int e0 = (nvec << 2) + tid;
    if (e0 < nnz) {
        g_rank[e0] = atomicAdd(&g_cnt[__ldg(rowp + e0)], 1);
        s += g_exp_lr[__ldg(relp + e0)];
    }

#pragma unroll
    for (int o = 16; o > 0; o >>= 1) s += __shfl_xor_sync(0xffffffffu, s, o);
    __shared__ float smf[8];
    if ((threadIdx.x & 31) == 0) smf[threadIdx.x >> 5] = s;
    __syncthreads();
    if (threadIdx.x < 32) {
        float v = (threadIdx.x < 8) ? smf[threadIdx.x] : 0.f;
#pragma unroll
        for (int o = 4; o > 0; o >>= 1) v += __shfl_xor_sync(0xffffffffu, v, o);
        if (threadIdx.x == 0) atomicAdd(&g_S, v);
    }
}

// ---------------------------------------------------------------------------
// K2: scan (98 co-resident blocks, monotonic barrier). Block 0 normalizes the
// coef table with 2^112 folded in for the gather's magic fp16 convert.
// ---------------------------------------------------------------------------
__global__ void __launch_bounds__(SCAN_BLK)
k_scan(int nnz) {
    __shared__ int sm[SCAN_BLK];
    const int t   = threadIdx.x;
    const int bid = blockIdx.x;
    const int gid = bid * SCAN_BLK + t;

    if (bid == 0) {
        const float invS112 = 5.192296858534828e33f / g_S;   // 2^112 / S
        for (int r = t; r < N_REL; r += SCAN_BLK) g_coef[r] = g_exp_lr[r] * invS112;
    }

    const int v = (gid < N_NODES) ? g_cnt[gid] : 0;
    sm[t] = v;
    __syncthreads();
#pragma unroll
    for (int o = 1; o < SCAN_BLK; o <<= 1) {
        const int p = (t >= o) ? sm[t - o] : 0;
        __syncthreads();
        sm[t] += p;
        __syncthreads();
    }
    const int incl = sm[t];
    if (t == SCAN_BLK - 1) g_bsum[bid] = incl;

    grid_bar<SCAN_NB>(&g_tick2);

    sm[t] = (t < bid) ? g_bsum[t] : 0;
    __syncthreads();
#pragma unroll
    for (int o = SCAN_BLK / 2; o > 0; o >>= 1) {
        if (t < o) sm[t] += sm[t + o];
        __syncthreads();
    }
    const int base = sm[0];

    if (gid < N_NODES) g_offs[gid] = base + incl - v;
    if (gid == N_NODES - 1) g_offs[N_NODES] = nnz;
}

// ---------------------------------------------------------------------------
// K3: reorder WITHOUT atomics (pos = offs[row] + rank), 8 edges per thread.
// ---------------------------------------------------------------------------
__global__ void __launch_bounds__(256)
k_reorder(const int* __restrict__ rowp, const int* __restrict__ colp,
          const int* __restrict__ relp, int nnz) {
    const int nvec = nnz >> 2;
    const int tid  = blockIdx.x * blockDim.x + threadIdx.x;

#pragma unroll
    for (int k = 0; k < 2; k++) {
        const int i = tid * 2 + k;
        if (i < nvec) {
            const int4 r  = __ldg(reinterpret_cast<const int4*>(rowp) + i);
            const int4 c  = __ldg(reinterpret_cast<const int4*>(colp) + i);
            const int4 q  = __ldg(reinterpret_cast<const int4*>(relp) + i);
            const int4 rk = __ldg(reinterpret_cast<const int4*>(g_rank) + i);
            const int p0 = __ldg(&g_offs[r.x]) + rk.x;
            const int p1 = __ldg(&g_offs[r.y]) + rk.y;
            const int p2 = __ldg(&g_offs[r.z]) + rk.z;
            const int p3 = __ldg(&g_offs[r.w]) + rk.w;
            g_edges[p0] = (unsigned)c.x | ((unsigned)q.x << 16);
            g_edges[p1] = (unsigned)c.y | ((unsigned)q.y << 16);
            g_edges[p2] = (unsigned)c.z | ((unsigned)q.z << 16);
            g_edges[p3] = (unsigned)c.w | ((unsigned)q.w << 16);
        }
    }
    const int e = (nvec << 2) + tid;
    if (e < nnz) {
        const int pos = __ldg(&g_offs[__ldg(rowp + e)]) + g_rank[e];
        g_edges[pos] = (unsigned)__ldg(colp + e) | ((unsigned)__ldg(relp + e) << 16);
    }
}

// ---------------------------------------------------------------------------
// K4: gather SpMM over fp16 features with magic-shift convert (no F2F).
//   f32(h) = as_float(((h&0x7FFF)<<13) | (sign<<16)) * 2^112, 2^112 in coef.
// Warp per row; per edge each lane loads uint2 (4 halves = 8B -> 256B/warp);
// 4 independent gathers in flight; coalesced fp32 store.
// ---------------------------------------------------------------------------
__device__ __forceinline__ void acc_h2(unsigned p, float cp, float& a, float& b) {
    // h0 = low half, h1 = high half
    const unsigned u0 = ((p << 13) & 0x0FFFE000u) | ((p << 16) & 0x80000000u);
    const unsigned u1 = ((p >> 3) & 0x0FFFE000u) | (p & 0x80000000u);
    a += cp * __uint_as_float(u0);
    b += cp * __uint_as_float(u1);
}

__device__ __forceinline__ void acc_edge(unsigned e, int lane, float4& a) {
    const int   col = (int)(e & 0xFFFFu);
    const float cp  = g_coef[e >> 16];              // includes 2^112
    const uint2 hv  = __ldg(reinterpret_cast<const uint2*>(
                                g_inh + (size_t)col * D) + lane);
    acc_h2(hv.x, cp, a.x, a.y);
    acc_h2(hv.y, cp, a.z, a.w);
}

__global__ void __launch_bounds__(256)
k_gather(float* __restrict__ out) {
    const int lane = threadIdx.x & 31;
    const int row  = (blockIdx.x * blockDim.x + threadIdx.x) >> 5;
    if (row >= N_NODES) return;

    const int s = __ldg(&g_offs[row]);
    const int e = __ldg(&g_offs[row + 1]);

    float4 a0 = make_float4(0.f, 0.f, 0.f, 0.f);
    float4 a1 = make_float4(0.f, 0.f, 0.f, 0.f);
    float4 a2 = make_float4(0.f, 0.f, 0.f, 0.f);
    float4 a3 = make_float4(0.f, 0.f, 0.f, 0.f);

    int i = s;
    while (i < e && (i & 3)) { acc_edge(__ldg(&g_edges[i]), lane, a0); i++; }
    for (; i + 3 < e; i += 4) {
        const uint4 p = __ldg(reinterpret_cast<const uint4*>(g_edges + i));
        acc_edge(p.x, lane, a0);
        acc_edge(p.y, lane, a1);
        acc_edge(p.z, lane, a2);
        acc_edge(p.w, lane, a3);
    }
    for (; i < e; i++) acc_edge(__ldg(&g_edges[i]), lane, a0);

    // lane owns halves [lane*4 .. lane*4+3] in order (h0,h1,h2,h3) = (x,y,z,w)
    a0.x += a1.x + a2.x + a3.x;
    a0.y += a1.y + a2.y + a3.y;
    a0.z += a1.z + a2.z + a3.z;
    a0.w += a1.w + a2.w + a3.w;
    reinterpret_cast<float4*>(out + (size_t)row * D)[lane] = a0;
}

// ---------------------------------------------------------------------------
// kernel_launch
// Inputs: 0 inlayer [N,D] f32 | 1 dual [R,D] f32 | 2 conv_w [D] f32
//         3 conv_b [1] f32    | 4 edge_idx [2,NNZ] i32 | 5 edge_rel [NNZ] i32
// Output: [N, D] f32
// ---------------------------------------------------------------------------
extern "C" void kernel_launch(void* const* d_in, const int* in_sizes, int n_in,
                              void* d_out, int out_size) {
    const float* inlayer = (const float*)d_in[0];
    const float* dual    = (const float*)d_in[1];
    const float* conv_w  = (const float*)d_in[2];
    const float* conv_b  = (const float*)d_in[3];
    const int*   eidx    = (const int*)d_in[4];
    const int*   erel    = (const int*)d_in[5];
    float*       out     = (float*)d_out;

    const int nnz = in_sizes[5];
    const int* rowp = eidx;
    const int* colp = eidx + nnz;

    k_fused<<<FUSE_NB, 256>>>(inlayer, dual, conv_w, conv_b, rowp, erel, nnz);
    k_scan<<<SCAN_NB, SCAN_BLK>>>(nnz);
    k_reorder<<<(nnz / 8 + 255) / 256, 256>>>(rowp, colp, erel, nnz);
    k_gather<<<(N_NODES * 32 + 255) / 256, 256>>>(out);
}